// round 5
// baseline (speedup 1.0000x reference)
#include <cuda_runtime.h>

// Problem constants (fixed by setup_inputs)
#define BATCH 2048
#define F 64
#define H 128
#define STEPS 101       // t + input_length
#define LFRAMES 102     // total_length
#define DT 0.1f

#define WARPS_PER_CTA 28
#define THREADS (WARPS_PER_CTA * 32)   // 896
#define GRID 148
#define NJOBS 4096                     // single-row jobs

// ---- SMEM layout (float offsets) ----
// Weights stored TRANSPOSED (out-major): Wt[o][i] = W[i][o].
// Pitches 68 (=17 x 16B) and 132 (=33 x 16B): odd 16B-group stride =>
// conflict-free LDS.128 for row-per-lane access; 16B-aligned rows.
#define PW1 68
#define PW 132
#define OFF_W1T 0                        // 128*68  = 8704
#define OFF_W2T (OFF_W1T + 128 * PW1)    // 8704
#define OFF_W3T (OFF_W2T + 128 * PW)     // 25600
#define OFF_B1  (OFF_W3T + 128 * PW)     // 42496
#define OFF_B2  (OFF_B1 + 128)
#define OFF_B3  (OFF_B2 + 128)
#define OFF_V   (OFF_B3 + 128)
#define OFF_BUF (OFF_V + 128)            // 43008 (16B aligned)
#define WARP_BUF 448                     // Y(64) | A(128) | B(128) | C(128)
#define SMEM_FLOATS (OFF_BUF + WARPS_PER_CTA * WARP_BUF)  // 55552 fl = 222208 B

// Backward-trajectory scratch (device global: allocation-free)
__device__ __align__(16) float g_back[(size_t)BATCH * LFRAMES * F];

__device__ __forceinline__ float mytanh(float x) { return tanhf(x); }

// Forward matvec (R=1): acc[q] = b[lane+32q] + sum_i a[i] * Wt[lane+32q][i]
template <int IN, int PITCH>
__device__ __forceinline__ void mv_fwd(const float* __restrict__ Wt,
                                       const float* __restrict__ bb,
                                       const float* __restrict__ abuf,
                                       float acc[4], int lane) {
  const float* w0 = Wt + lane * PITCH;
#pragma unroll
  for (int q = 0; q < 4; q++) acc[q] = bb[lane + 32 * q];
#pragma unroll 4
  for (int i = 0; i < IN; i += 4) {
    float4 a = *(const float4*)(abuf + i);          // warp-uniform broadcast
#pragma unroll
    for (int q = 0; q < 4; q++) {
      float4 w = *(const float4*)(w0 + 32 * q * PITCH + i);
      acc[q] += w.x * a.x;
      acc[q] += w.y * a.y;
      acc[q] += w.z * a.z;
      acc[q] += w.w * a.w;
    }
  }
}

// Backward matvec (R=1), 128 outputs: lane owns i = 4*lane + {0..3}.
// acc[j] = sum_o d[o] * Wt[o][4*lane + j]
__device__ __forceinline__ void mv_bwd128(const float* __restrict__ Wt,
                                          const float* __restrict__ dbuf,
                                          float acc[4], int lane) {
  const float* wc = Wt + 4 * lane;
#pragma unroll
  for (int j = 0; j < 4; j++) acc[j] = 0.0f;
#pragma unroll 4
  for (int o = 0; o < 128; o += 4) {
    float4 d = *(const float4*)(dbuf + o);          // broadcast
    float4 w;
    w = *(const float4*)(wc + (o + 0) * PW);
    acc[0] += d.x * w.x; acc[1] += d.x * w.y; acc[2] += d.x * w.z; acc[3] += d.x * w.w;
    w = *(const float4*)(wc + (o + 1) * PW);
    acc[0] += d.y * w.x; acc[1] += d.y * w.y; acc[2] += d.y * w.z; acc[3] += d.y * w.w;
    w = *(const float4*)(wc + (o + 2) * PW);
    acc[0] += d.z * w.x; acc[1] += d.z * w.y; acc[2] += d.z * w.z; acc[3] += d.z * w.w;
    w = *(const float4*)(wc + (o + 3) * PW);
    acc[0] += d.w * w.x; acc[1] += d.w * w.y; acc[2] += d.w * w.z; acc[3] += d.w * w.w;
  }
}

// Backward matvec (R=1), 64 outputs: lane owns i = 2*lane + {0,1} (W1t, pitch PW1)
__device__ __forceinline__ void mv_bwd64(const float* __restrict__ Wt,
                                         const float* __restrict__ dbuf,
                                         float acc[2], int lane) {
  const float* wc = Wt + 2 * lane;
  acc[0] = 0.0f; acc[1] = 0.0f;
#pragma unroll 4
  for (int o = 0; o < 128; o += 4) {
    float4 d = *(const float4*)(dbuf + o);          // broadcast
    float2 w;
    w = *(const float2*)(wc + (o + 0) * PW1);
    acc[0] += d.x * w.x; acc[1] += d.x * w.y;
    w = *(const float2*)(wc + (o + 1) * PW1);
    acc[0] += d.y * w.x; acc[1] += d.y * w.y;
    w = *(const float2*)(wc + (o + 2) * PW1);
    acc[0] += d.z * w.x; acc[1] += d.z * w.y;
    w = *(const float2*)(wc + (o + 3) * PW1);
    acc[0] += d.w * w.x; acc[1] += d.w * w.y;
  }
}

__global__ void __launch_bounds__(THREADS, 1)
ham_kernel(const float* __restrict__ x,
           const float* __restrict__ W1, const float* __restrict__ b1,
           const float* __restrict__ W2, const float* __restrict__ b2,
           const float* __restrict__ W3, const float* __restrict__ b3,
           const float* __restrict__ W4, const float* __restrict__ W5,
           float* __restrict__ out) {
  extern __shared__ float sm[];
  const int tid = threadIdx.x;

  // ---- Stage transposed weights ----
  for (int idx = tid; idx < 64 * 128; idx += THREADS) {
    int i = idx >> 7, o = idx & 127;
    sm[OFF_W1T + o * PW1 + i] = W1[idx];
  }
  for (int idx = tid; idx < 128 * 128; idx += THREADS) {
    int i = idx >> 7, o = idx & 127;
    sm[OFF_W2T + o * PW + i] = W2[idx];
    sm[OFF_W3T + o * PW + i] = W3[idx];
  }
  if (tid < H) {
    sm[OFF_B1 + tid] = b1[tid];
    sm[OFF_B2 + tid] = b2[tid];
    sm[OFF_B3 + tid] = b3[tid];
    float acc = 0.0f;  // v = W4 @ W5[:,0] (constant cotangent of h3)
    for (int k = 0; k < H; k++) acc += W4[tid * H + k] * W5[k];
    sm[OFF_V + tid] = acc;
  }
  __syncthreads();

  const int warp = tid >> 5;
  const int lane = tid & 31;
  const int gw = blockIdx.x * WARPS_PER_CTA + warp;  // 0..4143
  if (gw >= NJOBS) return;                           // 48 idle warps
  const bool bwd = (gw >= NJOBS / 2);
  const int b = bwd ? gw - NJOBS / 2 : gw;           // batch row

  float* bufY = sm + OFF_BUF + warp * WARP_BUF;      // [64]  (y stage / g)
  float* bufA = bufY + 64;                           // [128] h1
  float* bufB = bufA + 128;                          // [128] h2 / d1
  float* bufC = bufB + 128;                          // [128] d3 / d2

  const int f0 = 2 * lane;                           // owned features f0, f0+1
  // vflip sign: for bwd, -1 on features >= 32 (both of a lane's pair agree)
  const float sgnv = (!bwd || lane < 16) ? 1.0f : -1.0f;
  const float* xp = x + ((size_t)b * 2 + (bwd ? 1 : 0)) * F;
  float y0 = sgnv * xp[f0];
  float y1 = sgnv * xp[f0 + 1];
  float* gbase = (bwd ? g_back : out) + (size_t)b * LFRAMES * F;
  const float inv101 = 1.0f / 101.0f;

  {  // frame 0 (weight 1); backward frame k lands at index LFRAMES-1-k
    float* p = gbase + (bwd ? (LFRAMES - 1) : 0) * F;
    *(float2*)(p + f0) = make_float2(sgnv * y0, sgnv * y1);
  }

  // partner offset for symplectic swap: dyn[f] = +g[f+32] (f<32), -g[f-32]
  const int partner = f0 + ((lane < 16) ? 32 : -32);
  const float swsgn = (lane < 16) ? DT : -DT;

#pragma unroll 1
  for (int k = 1; k <= STEPS; k++) {
    __syncwarp();
    *(float2*)(bufY + f0) = make_float2(y0, y1);
    __syncwarp();

    float acc[4];

    // ---- fwd1: h1 = tanh(y@W1 + b1) ----
    mv_fwd<64, PW1>(sm + OFF_W1T, sm + OFF_B1, bufY, acc, lane);
    __syncwarp();
#pragma unroll
    for (int q = 0; q < 4; q++) bufA[lane + 32 * q] = mytanh(acc[q]);
    __syncwarp();

    // ---- fwd2: h2 = tanh(h1@W2 + b2) ----
    mv_fwd<128, PW>(sm + OFF_W2T, sm + OFF_B2, bufA, acc, lane);
    __syncwarp();
#pragma unroll
    for (int q = 0; q < 4; q++) bufB[lane + 32 * q] = mytanh(acc[q]);
    __syncwarp();

    // ---- fwd3: d3 = v * (1 - tanh(h2@W3 + b3)^2) ----
    mv_fwd<128, PW>(sm + OFF_W3T, sm + OFF_B3, bufB, acc, lane);
    __syncwarp();
#pragma unroll
    for (int q = 0; q < 4; q++) {
      float t = mytanh(acc[q]);
      bufC[lane + 32 * q] = sm[OFF_V + lane + 32 * q] * (1.0f - t * t);
    }
    __syncwarp();

    // ---- bwd1: d2 = (W3t^T-reduce over o of d3) * (1 - h2^2) ----
    mv_bwd128(sm + OFF_W3T, bufC, acc, lane);
    __syncwarp();          // all lanes done reading bufC
    {
      float4 h = *(const float4*)(bufB + 4 * lane);
      float4 dv = make_float4(acc[0] * (1.0f - h.x * h.x),
                              acc[1] * (1.0f - h.y * h.y),
                              acc[2] * (1.0f - h.z * h.z),
                              acc[3] * (1.0f - h.w * h.w));
      *(float4*)(bufC + 4 * lane) = dv;
    }
    __syncwarp();

    // ---- bwd2: d1 = (...d2) * (1 - h1^2) ----
    mv_bwd128(sm + OFF_W2T, bufC, acc, lane);
    __syncwarp();
    {
      float4 h = *(const float4*)(bufA + 4 * lane);
      float4 dv = make_float4(acc[0] * (1.0f - h.x * h.x),
                              acc[1] * (1.0f - h.y * h.y),
                              acc[2] * (1.0f - h.z * h.z),
                              acc[3] * (1.0f - h.w * h.w));
      *(float4*)(bufB + 4 * lane) = dv;   // h2 dead; d1 -> bufB
    }
    __syncwarp();

    // ---- bwd3: g = W1^T-reduce of d1 (64 outputs), to bufY ----
    float g2[2];
    mv_bwd64(sm + OFF_W1T, bufB, g2, lane);
    __syncwarp();          // lanes done reading bufY staging from fwd1? (dead) safe
    *(float2*)(bufY + f0) = make_float2(g2[0], g2[1]);
    __syncwarp();

    // ---- symplectic update: y[f] += DT * (f<32 ? g[f+32] : -g[f-32]) ----
    {
      float2 gp = *(const float2*)(bufY + partner);
      y0 += swsgn * gp.x;
      y1 += swsgn * gp.y;
    }

    // ---- emit weighted frame ----
    const float s = (float)(101 - k) * inv101;  // w0(k) fwd == w1(L-1-k) bwd
    float* p = gbase + (bwd ? (LFRAMES - 1 - k) : k) * F;
    *(float2*)(p + f0) = make_float2(sgnv * y0 * s, sgnv * y1 * s);
  }
}

__global__ void combine_kernel(float4* __restrict__ out, int n4) {
  const float4* __restrict__ gb = (const float4*)g_back;
  int i = blockIdx.x * blockDim.x + threadIdx.x;
  const int stride = gridDim.x * blockDim.x;
  for (; i < n4; i += stride) {
    float4 o = out[i];
    float4 g = gb[i];
    o.x += g.x; o.y += g.y; o.z += g.z; o.w += g.w;
    out[i] = o;
  }
}

extern "C" void kernel_launch(void* const* d_in, const int* in_sizes, int n_in,
                              void* d_out, int out_size) {
  (void)in_sizes; (void)n_in; (void)out_size;
  // metadata order: t, x, W1, b1, W2, b2, W3, b3, W4, b4, W5, b5
  const float* x  = (const float*)d_in[1];
  const float* W1 = (const float*)d_in[2];
  const float* b1 = (const float*)d_in[3];
  const float* W2 = (const float*)d_in[4];
  const float* b2 = (const float*)d_in[5];
  const float* W3 = (const float*)d_in[6];
  const float* b3 = (const float*)d_in[7];
  const float* W4 = (const float*)d_in[8];
  const float* W5 = (const float*)d_in[10];
  float* out = (float*)d_out;

  cudaFuncSetAttribute(ham_kernel, cudaFuncAttributeMaxDynamicSharedMemorySize,
                       SMEM_FLOATS * (int)sizeof(float));

  ham_kernel<<<GRID, THREADS, SMEM_FLOATS * (int)sizeof(float)>>>(
      x, W1, b1, W2, b2, W3, b3, W4, W5, out);

  const int n4 = (BATCH * LFRAMES * F) / 4;
  combine_kernel<<<1024, 256>>>((float4*)out, n4);
}

// round 6
// speedup vs baseline: 1.9429x; 1.9429x over previous
#include <cuda_runtime.h>

// Problem constants (fixed by setup_inputs)
#define BATCH 2048
#define F 64
#define H 128
#define STEPS 101       // t + input_length = 100 + 1
#define LFRAMES 102     // total_length
#define DT 0.1f

#define GRID 148
#define THREADS 256     // 8 warps: w0-3 take 4 rows, w4-7 take 3 rows
#define NROWS 4096      // 2048 fwd + 2048 bwd row-jobs
#define ROWS_PER_CTA 28

// SMEM layout (float offsets). Pitch 129 => conflict-free for both
// row-contiguous (forward) and row-strided (transposed/backward) access.
#define P1 129
#define OFF_W1 0
#define OFF_W2 (OFF_W1 + 64 * P1)      // 8256
#define OFF_W3 (OFF_W2 + 128 * P1)     // 24768
#define OFF_B1 (OFF_W3 + 128 * P1)     // 41280
#define OFF_B2 (OFF_B1 + 128)
#define OFF_B3 (OFF_B2 + 128)
#define OFF_V  (OFF_B3 + 128)
#define OFF_BUF (OFF_V + 128)          // 41792
#define WARP_BUF 1280                  // per-warp: bufY 256 + bufA 512 + bufB 512
#define SMEM_FLOATS (OFF_BUF + 8 * WARP_BUF)  // 52032 floats = 208128 B

// Backward-trajectory scratch (device global: allocation-free)
__device__ __align__(16) float g_back[(size_t)BATCH * LFRAMES * F];

__device__ __forceinline__ float mytanh(float x) { return tanhf(x); }

// Forward matvec: acc[q][r] += sum_i buf[r][i] * W[i][lane+32q]
template <int IN, int NR>
__device__ __forceinline__ void matvec_fwd(const float* __restrict__ Wsm,
                                           const float* __restrict__ buf,
                                           float acc[4][NR], int lane) {
#pragma unroll 1
  for (int i = 0; i < IN; i += 4) {
    float4 a[NR];
#pragma unroll
    for (int r = 0; r < NR; r++) a[r] = *(const float4*)(buf + r * IN + i);
    const float* wrow = Wsm + i * P1 + lane;
#pragma unroll
    for (int ii = 0; ii < 4; ii++) {
#pragma unroll
      for (int q = 0; q < 4; q++) {
        float w = wrow[ii * P1 + 32 * q];
#pragma unroll
        for (int r = 0; r < NR; r++)
          acc[q][r] += w * ((const float*)&a[r])[ii];
      }
    }
  }
}

// Backward (transposed) matvec: acc[q][r] += sum_j W[lane+32q][j] * buf[r][j]
template <int QN, int NR>
__device__ __forceinline__ void matvec_bwd(const float* __restrict__ Wsm,
                                           const float* __restrict__ buf,
                                           float acc[QN][NR], int lane) {
  const float* wr[QN];
#pragma unroll
  for (int q = 0; q < QN; q++) wr[q] = Wsm + (lane + 32 * q) * P1;
#pragma unroll 1
  for (int j = 0; j < 128; j += 4) {
    float4 d[NR];
#pragma unroll
    for (int r = 0; r < NR; r++) d[r] = *(const float4*)(buf + r * 128 + j);
#pragma unroll
    for (int jj = 0; jj < 4; jj++) {
#pragma unroll
      for (int q = 0; q < QN; q++) {
        float w = wr[q][j + jj];
#pragma unroll
        for (int r = 0; r < NR; r++)
          acc[q][r] += w * ((const float*)&d[r])[jj];
      }
    }
  }
}

template <int NR>
__device__ __forceinline__ void run_job(float* __restrict__ sm, int warp,
                                        int lane, int row0,
                                        const float* __restrict__ x,
                                        float* __restrict__ out) {
  float* bufY = sm + OFF_BUF + warp * WARP_BUF;  // [NR][64]
  float* bufA = bufY + 256;                      // [NR][128]
  float* bufB = bufY + 768;                      // [NR][128]

  float y0[NR], y1[NR];
  float* obase[NR];
  float sgn[NR];
  bool bwdr[NR];
#pragma unroll
  for (int r = 0; r < NR; r++) {
    int row = row0 + r;
    if (row > NROWS - 1) row = NROWS - 1;   // clamp: duplicates are identical
    const bool bwd = (row >= NROWS / 2);
    const int b = row & (BATCH - 1);
    bwdr[r] = bwd;
    sgn[r] = bwd ? -1.0f : 1.0f;
    const float* xp = x + ((size_t)b * 2 + (bwd ? 1 : 0)) * F;
    y0[r] = xp[lane];
    y1[r] = sgn[r] * xp[lane + 32];  // vflip on backward init
    obase[r] = (bwd ? g_back : out) + (size_t)b * LFRAMES * F;
  }
  const float inv101 = 1.0f / 101.0f;

  // frame 0 (weight = 1); backward frame k lands at index LFRAMES-1-k
#pragma unroll
  for (int r = 0; r < NR; r++) {
    float* p = obase[r] + (bwdr[r] ? (LFRAMES - 1) : 0) * F;
    p[lane] = y0[r];
    p[lane + 32] = sgn[r] * y1[r];
  }

#pragma unroll 1
  for (int k = 1; k <= STEPS; k++) {
    __syncwarp();
#pragma unroll
    for (int r = 0; r < NR; r++) {
      bufY[r * 64 + lane] = y0[r];
      bufY[r * 64 + 32 + lane] = y1[r];
    }
    __syncwarp();

    float h1v[4][NR], h2v[4][NR], acc[4][NR];

    // ---- stage 1: h1 = tanh(y@W1 + b1) ----
#pragma unroll
    for (int q = 0; q < 4; q++) {
      float b = sm[OFF_B1 + lane + 32 * q];
#pragma unroll
      for (int r = 0; r < NR; r++) acc[q][r] = b;
    }
    matvec_fwd<64, NR>(sm + OFF_W1, bufY, acc, lane);
#pragma unroll
    for (int q = 0; q < 4; q++)
#pragma unroll
      for (int r = 0; r < NR; r++) h1v[q][r] = mytanh(acc[q][r]);
    __syncwarp();
#pragma unroll
    for (int q = 0; q < 4; q++)
#pragma unroll
      for (int r = 0; r < NR; r++) bufA[r * 128 + lane + 32 * q] = h1v[q][r];
    __syncwarp();

    // ---- stage 2: h2 = tanh(h1@W2 + b2) ----
#pragma unroll
    for (int q = 0; q < 4; q++) {
      float b = sm[OFF_B2 + lane + 32 * q];
#pragma unroll
      for (int r = 0; r < NR; r++) acc[q][r] = b;
    }
    matvec_fwd<128, NR>(sm + OFF_W2, bufA, acc, lane);
#pragma unroll
    for (int q = 0; q < 4; q++)
#pragma unroll
      for (int r = 0; r < NR; r++) h2v[q][r] = mytanh(acc[q][r]);
    __syncwarp();
#pragma unroll
    for (int q = 0; q < 4; q++)
#pragma unroll
      for (int r = 0; r < NR; r++) bufB[r * 128 + lane + 32 * q] = h2v[q][r];
    __syncwarp();

    // ---- stage 3: h3 = tanh(h2@W3 + b3); d3 = v * (1 - h3^2) ----
#pragma unroll
    for (int q = 0; q < 4; q++) {
      float b = sm[OFF_B3 + lane + 32 * q];
#pragma unroll
      for (int r = 0; r < NR; r++) acc[q][r] = b;
    }
    matvec_fwd<128, NR>(sm + OFF_W3, bufB, acc, lane);
    __syncwarp();
#pragma unroll
    for (int q = 0; q < 4; q++) {
      float vq = sm[OFF_V + lane + 32 * q];
#pragma unroll
      for (int r = 0; r < NR; r++) {
        float t = mytanh(acc[q][r]);
        bufA[r * 128 + lane + 32 * q] = vq * (1.0f - t * t);  // d3
      }
    }
    __syncwarp();

    // ---- backward 1: d2 = (W3 @ d3) * (1 - h2^2) ----
#pragma unroll
    for (int q = 0; q < 4; q++)
#pragma unroll
      for (int r = 0; r < NR; r++) acc[q][r] = 0.0f;
    matvec_bwd<4, NR>(sm + OFF_W3, bufA, acc, lane);
    __syncwarp();
#pragma unroll
    for (int q = 0; q < 4; q++)
#pragma unroll
      for (int r = 0; r < NR; r++)
        bufB[r * 128 + lane + 32 * q] =
            acc[q][r] * (1.0f - h2v[q][r] * h2v[q][r]);
    __syncwarp();

    // ---- backward 2: d1 = (W2 @ d2) * (1 - h1^2) ----
#pragma unroll
    for (int q = 0; q < 4; q++)
#pragma unroll
      for (int r = 0; r < NR; r++) acc[q][r] = 0.0f;
    matvec_bwd<4, NR>(sm + OFF_W2, bufB, acc, lane);
    __syncwarp();
#pragma unroll
    for (int q = 0; q < 4; q++)
#pragma unroll
      for (int r = 0; r < NR; r++)
        bufA[r * 128 + lane + 32 * q] =
            acc[q][r] * (1.0f - h1v[q][r] * h1v[q][r]);
    __syncwarp();

    // ---- backward 3: g = W1 @ d1 (64 outputs: q = 0,1) ----
    float gacc[2][NR];
#pragma unroll
    for (int q = 0; q < 2; q++)
#pragma unroll
      for (int r = 0; r < NR; r++) gacc[q][r] = 0.0f;
    matvec_bwd<2, NR>(sm + OFF_W1, bufA, gacc, lane);

    // ---- symplectic-style update + emit weighted frame ----
    const float s = (float)(101 - k) * inv101;  // w0(k) fwd == w1(L-1-k) bwd
#pragma unroll
    for (int r = 0; r < NR; r++) {
      y0[r] += DT * gacc[1][r];  // f = lane    (< 32): +g[f+32]
      y1[r] -= DT * gacc[0][r];  // f = lane+32 (>=32): -g[f-32]
      float* p = obase[r] + (bwdr[r] ? (LFRAMES - 1 - k) : k) * F;
      p[lane] = y0[r] * s;
      p[lane + 32] = sgn[r] * y1[r] * s;
    }
  }
}

__global__ void __launch_bounds__(THREADS, 1)
ham_kernel(const float* __restrict__ x,
           const float* __restrict__ W1, const float* __restrict__ b1,
           const float* __restrict__ W2, const float* __restrict__ b2,
           const float* __restrict__ W3, const float* __restrict__ b3,
           const float* __restrict__ W4, const float* __restrict__ W5,
           float* __restrict__ out) {
  extern __shared__ float sm[];
  const int tid = threadIdx.x;

  // ---- Stage weights into SMEM (pitch P1) ----
  for (int idx = tid; idx < 64 * H; idx += THREADS)
    sm[OFF_W1 + (idx >> 7) * P1 + (idx & 127)] = W1[idx];
  for (int idx = tid; idx < H * H; idx += THREADS)
    sm[OFF_W2 + (idx >> 7) * P1 + (idx & 127)] = W2[idx];
  for (int idx = tid; idx < H * H; idx += THREADS)
    sm[OFF_W3 + (idx >> 7) * P1 + (idx & 127)] = W3[idx];
  for (int idx = tid; idx < H; idx += THREADS) {
    sm[OFF_B1 + idx] = b1[idx];
    sm[OFF_B2 + idx] = b2[idx];
    sm[OFF_B3 + idx] = b3[idx];
  }
  if (tid < H) {  // v = W4 @ W5[:,0] (constant cotangent of h3)
    float acc = 0.0f;
    for (int k = 0; k < H; k++) acc += W4[tid * H + k] * W5[k];
    sm[OFF_V + tid] = acc;
  }
  __syncthreads();

  const int warp = tid >> 5;
  const int lane = tid & 31;

  // Warps 0-3 (one per SMSP) take 4 rows; warps 4-7 take 3 rows.
  // => every SMSP carries exactly 7 rows (ideal 6.92).
  const int cta_base = blockIdx.x * ROWS_PER_CTA;
  if (warp < 4) {
    const int row0 = cta_base + warp * 4;
    run_job<4>(sm, warp, lane, row0, x, out);
  } else {
    const int row0 = cta_base + 16 + (warp - 4) * 3;
    run_job<3>(sm, warp, lane, row0, x, out);
  }
}

__global__ void combine_kernel(float4* __restrict__ out, int n4) {
  const float4* __restrict__ gb = (const float4*)g_back;
  int i = blockIdx.x * blockDim.x + threadIdx.x;
  const int stride = gridDim.x * blockDim.x;
  for (; i < n4; i += stride) {
    float4 o = out[i];
    float4 g = gb[i];
    o.x += g.x; o.y += g.y; o.z += g.z; o.w += g.w;
    out[i] = o;
  }
}

extern "C" void kernel_launch(void* const* d_in, const int* in_sizes, int n_in,
                              void* d_out, int out_size) {
  (void)in_sizes; (void)n_in; (void)out_size;
  // metadata order: t, x, W1, b1, W2, b2, W3, b3, W4, b4, W5, b5
  const float* x  = (const float*)d_in[1];
  const float* W1 = (const float*)d_in[2];
  const float* b1 = (const float*)d_in[3];
  const float* W2 = (const float*)d_in[4];
  const float* b2 = (const float*)d_in[5];
  const float* W3 = (const float*)d_in[6];
  const float* b3 = (const float*)d_in[7];
  const float* W4 = (const float*)d_in[8];
  const float* W5 = (const float*)d_in[10];
  float* out = (float*)d_out;

  cudaFuncSetAttribute(ham_kernel, cudaFuncAttributeMaxDynamicSharedMemorySize,
                       SMEM_FLOATS * (int)sizeof(float));

  ham_kernel<<<GRID, THREADS, SMEM_FLOATS * (int)sizeof(float)>>>(
      x, W1, b1, W2, b2, W3, b3, W4, W5, out);

  const int n4 = (BATCH * LFRAMES * F) / 4;
  combine_kernel<<<1024, 256>>>((float4*)out, n4);
}

// round 7
// speedup vs baseline: 1.9431x; 1.0001x over previous
#include <cuda_runtime.h>

// Problem constants (fixed by setup_inputs)
#define BATCH 2048
#define F 64
#define H 128
#define STEPS 101       // t + input_length = 100 + 1
#define LFRAMES 102     // total_length
#define DT 0.1f

#define GRID 148
#define THREADS 256     // 8 warps: w0-3 take 4 rows, w4-7 take 3 rows
#define NROWS 4096      // 2048 fwd + 2048 bwd row-jobs
#define ROWS_PER_CTA 28

// SMEM layout (float offsets). Pitch 129 => conflict-free for both
// row-contiguous (forward) and row-strided (transposed/backward) access.
#define P1 129
#define OFF_W1 0
#define OFF_W2 (OFF_W1 + 64 * P1)      // 8256
#define OFF_W3 (OFF_W2 + 128 * P1)     // 24768
#define OFF_B1 (OFF_W3 + 128 * P1)     // 41280
#define OFF_B2 (OFF_B1 + 128)
#define OFF_B3 (OFF_B2 + 128)
#define OFF_V  (OFF_B3 + 128)
#define OFF_BUF (OFF_V + 128)          // 41792
#define WARP_BUF 1280                  // per-warp: bufY 256 + bufA 512 + bufB 512
#define SMEM_FLOATS (OFF_BUF + 8 * WARP_BUF)  // 52032 floats = 208128 B

// Backward-trajectory scratch (device global: allocation-free)
__device__ __align__(16) float g_back[(size_t)BATCH * LFRAMES * F];

__device__ __forceinline__ float mytanh(float x) { return tanhf(x); }

// Forward matvec: acc[q][r] += sum_i buf[r][i] * W[i][lane+32q]
template <int IN, int NR>
__device__ __forceinline__ void matvec_fwd(const float* __restrict__ Wsm,
                                           const float* __restrict__ buf,
                                           float acc[4][NR], int lane) {
#pragma unroll 1
  for (int i = 0; i < IN; i += 4) {
    float4 a[NR];
#pragma unroll
    for (int r = 0; r < NR; r++) a[r] = *(const float4*)(buf + r * IN + i);
    const float* wrow = Wsm + i * P1 + lane;
#pragma unroll
    for (int ii = 0; ii < 4; ii++) {
#pragma unroll
      for (int q = 0; q < 4; q++) {
        float w = wrow[ii * P1 + 32 * q];
#pragma unroll
        for (int r = 0; r < NR; r++)
          acc[q][r] += w * ((const float*)&a[r])[ii];
      }
    }
  }
}

// Backward (transposed) matvec: acc[q][r] += sum_j W[lane+32q][j] * buf[r][j]
template <int QN, int NR>
__device__ __forceinline__ void matvec_bwd(const float* __restrict__ Wsm,
                                           const float* __restrict__ buf,
                                           float acc[QN][NR], int lane) {
  const float* wr[QN];
#pragma unroll
  for (int q = 0; q < QN; q++) wr[q] = Wsm + (lane + 32 * q) * P1;
#pragma unroll 1
  for (int j = 0; j < 128; j += 4) {
    float4 d[NR];
#pragma unroll
    for (int r = 0; r < NR; r++) d[r] = *(const float4*)(buf + r * 128 + j);
#pragma unroll
    for (int jj = 0; jj < 4; jj++) {
#pragma unroll
      for (int q = 0; q < QN; q++) {
        float w = wr[q][j + jj];
#pragma unroll
        for (int r = 0; r < NR; r++)
          acc[q][r] += w * ((const float*)&d[r])[jj];
      }
    }
  }
}

template <int NR>
__device__ __forceinline__ void run_job(float* __restrict__ sm, int warp,
                                        int lane, int row0,
                                        const float* __restrict__ x,
                                        float* __restrict__ out) {
  float* bufY = sm + OFF_BUF + warp * WARP_BUF;  // [NR][64]
  float* bufA = bufY + 256;                      // [NR][128]
  float* bufB = bufY + 768;                      // [NR][128]

  float y0[NR], y1[NR];
  float* obase[NR];
  float sgn[NR];
  bool bwdr[NR];
#pragma unroll
  for (int r = 0; r < NR; r++) {
    int row = row0 + r;
    if (row > NROWS - 1) row = NROWS - 1;   // clamp: duplicates are identical
    const bool bwd = (row >= NROWS / 2);
    const int b = row & (BATCH - 1);
    bwdr[r] = bwd;
    sgn[r] = bwd ? -1.0f : 1.0f;
    const float* xp = x + ((size_t)b * 2 + (bwd ? 1 : 0)) * F;
    y0[r] = xp[lane];
    y1[r] = sgn[r] * xp[lane + 32];  // vflip on backward init
    obase[r] = (bwd ? g_back : out) + (size_t)b * LFRAMES * F;
  }
  const float inv101 = 1.0f / 101.0f;

  // frame 0 (weight = 1); backward frame k lands at index LFRAMES-1-k
#pragma unroll
  for (int r = 0; r < NR; r++) {
    float* p = obase[r] + (bwdr[r] ? (LFRAMES - 1) : 0) * F;
    p[lane] = y0[r];
    p[lane + 32] = sgn[r] * y1[r];
  }

#pragma unroll 1
  for (int k = 1; k <= STEPS; k++) {
    __syncwarp();
#pragma unroll
    for (int r = 0; r < NR; r++) {
      bufY[r * 64 + lane] = y0[r];
      bufY[r * 64 + 32 + lane] = y1[r];
    }
    __syncwarp();

    float h1v[4][NR], h2v[4][NR], acc[4][NR];

    // ---- stage 1: h1 = tanh(y@W1 + b1) ----
#pragma unroll
    for (int q = 0; q < 4; q++) {
      float b = sm[OFF_B1 + lane + 32 * q];
#pragma unroll
      for (int r = 0; r < NR; r++) acc[q][r] = b;
    }
    matvec_fwd<64, NR>(sm + OFF_W1, bufY, acc, lane);
#pragma unroll
    for (int q = 0; q < 4; q++)
#pragma unroll
      for (int r = 0; r < NR; r++) h1v[q][r] = mytanh(acc[q][r]);
    __syncwarp();
#pragma unroll
    for (int q = 0; q < 4; q++)
#pragma unroll
      for (int r = 0; r < NR; r++) bufA[r * 128 + lane + 32 * q] = h1v[q][r];
    __syncwarp();

    // ---- stage 2: h2 = tanh(h1@W2 + b2) ----
#pragma unroll
    for (int q = 0; q < 4; q++) {
      float b = sm[OFF_B2 + lane + 32 * q];
#pragma unroll
      for (int r = 0; r < NR; r++) acc[q][r] = b;
    }
    matvec_fwd<128, NR>(sm + OFF_W2, bufA, acc, lane);
#pragma unroll
    for (int q = 0; q < 4; q++)
#pragma unroll
      for (int r = 0; r < NR; r++) h2v[q][r] = mytanh(acc[q][r]);
    __syncwarp();
#pragma unroll
    for (int q = 0; q < 4; q++)
#pragma unroll
      for (int r = 0; r < NR; r++) bufB[r * 128 + lane + 32 * q] = h2v[q][r];
    __syncwarp();

    // ---- stage 3: h3 = tanh(h2@W3 + b3); d3 = v * (1 - h3^2) ----
#pragma unroll
    for (int q = 0; q < 4; q++) {
      float b = sm[OFF_B3 + lane + 32 * q];
#pragma unroll
      for (int r = 0; r < NR; r++) acc[q][r] = b;
    }
    matvec_fwd<128, NR>(sm + OFF_W3, bufB, acc, lane);
    __syncwarp();
#pragma unroll
    for (int q = 0; q < 4; q++) {
      float vq = sm[OFF_V + lane + 32 * q];
#pragma unroll
      for (int r = 0; r < NR; r++) {
        float t = mytanh(acc[q][r]);
        bufA[r * 128 + lane + 32 * q] = vq * (1.0f - t * t);  // d3
      }
    }
    __syncwarp();

    // ---- backward 1: d2 = (W3 @ d3) * (1 - h2^2) ----
#pragma unroll
    for (int q = 0; q < 4; q++)
#pragma unroll
      for (int r = 0; r < NR; r++) acc[q][r] = 0.0f;
    matvec_bwd<4, NR>(sm + OFF_W3, bufA, acc, lane);
    __syncwarp();
#pragma unroll
    for (int q = 0; q < 4; q++)
#pragma unroll
      for (int r = 0; r < NR; r++)
        bufB[r * 128 + lane + 32 * q] =
            acc[q][r] * (1.0f - h2v[q][r] * h2v[q][r]);
    __syncwarp();

    // ---- backward 2: d1 = (W2 @ d2) * (1 - h1^2) ----
#pragma unroll
    for (int q = 0; q < 4; q++)
#pragma unroll
      for (int r = 0; r < NR; r++) acc[q][r] = 0.0f;
    matvec_bwd<4, NR>(sm + OFF_W2, bufB, acc, lane);
    __syncwarp();
#pragma unroll
    for (int q = 0; q < 4; q++)
#pragma unroll
      for (int r = 0; r < NR; r++)
        bufA[r * 128 + lane + 32 * q] =
            acc[q][r] * (1.0f - h1v[q][r] * h1v[q][r]);
    __syncwarp();

    // ---- backward 3: g = W1 @ d1 (64 outputs: q = 0,1) ----
    float gacc[2][NR];
#pragma unroll
    for (int q = 0; q < 2; q++)
#pragma unroll
      for (int r = 0; r < NR; r++) gacc[q][r] = 0.0f;
    matvec_bwd<2, NR>(sm + OFF_W1, bufA, gacc, lane);

    // ---- symplectic-style update + emit weighted frame ----
    const float s = (float)(101 - k) * inv101;  // w0(k) fwd == w1(L-1-k) bwd
#pragma unroll
    for (int r = 0; r < NR; r++) {
      y0[r] += DT * gacc[1][r];  // f = lane    (< 32): +g[f+32]
      y1[r] -= DT * gacc[0][r];  // f = lane+32 (>=32): -g[f-32]
      float* p = obase[r] + (bwdr[r] ? (LFRAMES - 1 - k) : k) * F;
      p[lane] = y0[r] * s;
      p[lane + 32] = sgn[r] * y1[r] * s;
    }
  }
}

__global__ void __launch_bounds__(THREADS, 1)
ham_kernel(const float* __restrict__ x,
           const float* __restrict__ W1, const float* __restrict__ b1,
           const float* __restrict__ W2, const float* __restrict__ b2,
           const float* __restrict__ W3, const float* __restrict__ b3,
           const float* __restrict__ W4, const float* __restrict__ W5,
           float* __restrict__ out) {
  extern __shared__ float sm[];
  const int tid = threadIdx.x;

  // ---- Stage weights into SMEM (pitch P1) ----
  for (int idx = tid; idx < 64 * H; idx += THREADS)
    sm[OFF_W1 + (idx >> 7) * P1 + (idx & 127)] = W1[idx];
  for (int idx = tid; idx < H * H; idx += THREADS)
    sm[OFF_W2 + (idx >> 7) * P1 + (idx & 127)] = W2[idx];
  for (int idx = tid; idx < H * H; idx += THREADS)
    sm[OFF_W3 + (idx >> 7) * P1 + (idx & 127)] = W3[idx];
  for (int idx = tid; idx < H; idx += THREADS) {
    sm[OFF_B1 + idx] = b1[idx];
    sm[OFF_B2 + idx] = b2[idx];
    sm[OFF_B3 + idx] = b3[idx];
  }
  if (tid < H) {  // v = W4 @ W5[:,0] (constant cotangent of h3)
    float acc = 0.0f;
    for (int k = 0; k < H; k++) acc += W4[tid * H + k] * W5[k];
    sm[OFF_V + tid] = acc;
  }
  __syncthreads();

  const int warp = tid >> 5;
  const int lane = tid & 31;

  // Warps 0-3 (one per SMSP) take 4 rows; warps 4-7 take 3 rows.
  // => every SMSP carries exactly 7 rows (ideal 6.92).
  const int cta_base = blockIdx.x * ROWS_PER_CTA;
  if (warp < 4) {
    const int row0 = cta_base + warp * 4;
    run_job<4>(sm, warp, lane, row0, x, out);
  } else {
    const int row0 = cta_base + 16 + (warp - 4) * 3;
    run_job<3>(sm, warp, lane, row0, x, out);
  }
}

__global__ void combine_kernel(float4* __restrict__ out, int n4) {
  const float4* __restrict__ gb = (const float4*)g_back;
  int i = blockIdx.x * blockDim.x + threadIdx.x;
  const int stride = gridDim.x * blockDim.x;
  for (; i < n4; i += stride) {
    float4 o = out[i];
    float4 g = gb[i];
    o.x += g.x; o.y += g.y; o.z += g.z; o.w += g.w;
    out[i] = o;
  }
}

extern "C" void kernel_launch(void* const* d_in, const int* in_sizes, int n_in,
                              void* d_out, int out_size) {
  (void)in_sizes; (void)n_in; (void)out_size;
  // metadata order: t, x, W1, b1, W2, b2, W3, b3, W4, b4, W5, b5
  const float* x  = (const float*)d_in[1];
  const float* W1 = (const float*)d_in[2];
  const float* b1 = (const float*)d_in[3];
  const float* W2 = (const float*)d_in[4];
  const float* b2 = (const float*)d_in[5];
  const float* W3 = (const float*)d_in[6];
  const float* b3 = (const float*)d_in[7];
  const float* W4 = (const float*)d_in[8];
  const float* W5 = (const float*)d_in[10];
  float* out = (float*)d_out;

  cudaFuncSetAttribute(ham_kernel, cudaFuncAttributeMaxDynamicSharedMemorySize,
                       SMEM_FLOATS * (int)sizeof(float));

  ham_kernel<<<GRID, THREADS, SMEM_FLOATS * (int)sizeof(float)>>>(
      x, W1, b1, W2, b2, W3, b3, W4, W5, out);

  const int n4 = (BATCH * LFRAMES * F) / 4;
  combine_kernel<<<1024, 256>>>((float4*)out, n4);
}